// round 10
// baseline (speedup 1.0000x reference)
#include <cuda_runtime.h>
#include <cuda_bf16.h>
#include <cstdint>
#include <cmath>

// ---------------------------------------------------------------------------
// GroupedQueryAttention: B=2, T=2048, DIM=2048, H=16, KH=4, DK=DV=128
// d_out = [ out (2,2048,2048) fp32 | attn_weight (2,16,2048,2048) fp32 ]
//
// Round 7: kernel fusion for pipe overlap —
//   * Q/K/V projections in ONE launch (one wave tail)
//   * Wo projection + AW normalize in ONE launch (normalize soaks idle HBM
//     under the tensor-bound gemm)
//   * GEMM mainloop: single __syncthreads per BK iteration
// Attention unchanged from round 6. Split-bf16 3-term numerics everywhere.
// ---------------------------------------------------------------------------

#define BT 4096
#define DIM 2048
#define KVDIM 512
#define T 2048

// ---- device scratch (no allocation allowed) ----
__device__ __nv_bfloat16 g_qh[BT * DIM],  g_ql[BT * DIM];
__device__ __nv_bfloat16 g_kh[BT * DIM],  g_kl[BT * DIM];
__device__ __nv_bfloat16 g_vh[BT * DIM],  g_vl[BT * DIM];
__device__ __nv_bfloat16 g_Wqh[DIM * DIM], g_Wql[DIM * DIM];
__device__ __nv_bfloat16 g_Wkh[DIM * KVDIM], g_Wkl[DIM * KVDIM];
__device__ __nv_bfloat16 g_Wvh[DIM * KVDIM], g_Wvl[DIM * KVDIM];
__device__ __nv_bfloat16 g_Woh[DIM * DIM], g_Wol[DIM * DIM];
__device__ __nv_bfloat16 g_Qh[BT * DIM],  g_Ql[BT * DIM];
__device__ __nv_bfloat16 g_Kh[BT * KVDIM], g_Kl[BT * KVDIM];
__device__ __nv_bfloat16 g_Vh[BT * KVDIM], g_Vl[BT * KVDIM];
__device__ __nv_bfloat16 g_Oh[BT * DIM],  g_Ol[BT * DIM];
__device__ float g_invL[32 * T];

// ---------------------------------------------------------------------------
// helpers
// ---------------------------------------------------------------------------
__device__ __forceinline__ uint32_t smem_u32(const void* p) {
    return (uint32_t)__cvta_generic_to_shared(p);
}
__device__ __forceinline__ void ldsm_x4(uint32_t* r, uint32_t addr) {
    asm volatile("ldmatrix.sync.aligned.m8n8.x4.shared.b16 {%0,%1,%2,%3}, [%4];"
                 : "=r"(r[0]), "=r"(r[1]), "=r"(r[2]), "=r"(r[3]) : "r"(addr));
}
__device__ __forceinline__ void ldsm_x4t(uint32_t* r, uint32_t addr) {
    asm volatile("ldmatrix.sync.aligned.m8n8.x4.trans.shared.b16 {%0,%1,%2,%3}, [%4];"
                 : "=r"(r[0]), "=r"(r[1]), "=r"(r[2]), "=r"(r[3]) : "r"(addr));
}
__device__ __forceinline__ void mma16816(float* c, const uint32_t* a, const uint32_t* b) {
    asm volatile(
        "mma.sync.aligned.m16n8k16.row.col.f32.bf16.bf16.f32 "
        "{%0,%1,%2,%3}, {%4,%5,%6,%7}, {%8,%9}, {%0,%1,%2,%3};\n"
        : "+f"(c[0]), "+f"(c[1]), "+f"(c[2]), "+f"(c[3])
        : "r"(a[0]), "r"(a[1]), "r"(a[2]), "r"(a[3]), "r"(b[0]), "r"(b[1]));
}
__device__ __forceinline__ void cp16(uint32_t saddr, const void* g) {
    asm volatile("cp.async.cg.shared.global [%0], [%1], 16;" :: "r"(saddr), "l"(g));
}
#define CP_COMMIT() asm volatile("cp.async.commit_group;")
#define CP_WAIT0()  asm volatile("cp.async.wait_group 0;")

__device__ __forceinline__ __nv_bfloat162 pack_hi(float a, float b) {
    __nv_bfloat162 r; r.x = __float2bfloat16(a); r.y = __float2bfloat16(b); return r;
}
__device__ __forceinline__ __nv_bfloat162 pack_lo(float a, float b, __nv_bfloat162 h) {
    __nv_bfloat162 r;
    r.x = __float2bfloat16(a - __bfloat162float(h.x));
    r.y = __float2bfloat16(b - __bfloat162float(h.y));
    return r;
}

// ---------------------------------------------------------------------------
// split: fp32 -> bf16 hi/lo; blockIdx.y selects one of up to 3 tensors
// ---------------------------------------------------------------------------
__global__ void split3_kernel(
    const float* __restrict__ s0, __nv_bfloat16* __restrict__ h0, __nv_bfloat16* __restrict__ l0,
    const float* __restrict__ s1, __nv_bfloat16* __restrict__ h1, __nv_bfloat16* __restrict__ l1,
    const float* __restrict__ s2, __nv_bfloat16* __restrict__ h2, __nv_bfloat16* __restrict__ l2,
    int n4)
{
    int i = blockIdx.x * blockDim.x + threadIdx.x;
    if (i >= n4) return;
    const float* src; __nv_bfloat16 *h, *l;
    if (blockIdx.y == 0)      { src = s0; h = h0; l = l0; }
    else if (blockIdx.y == 1) { src = s1; h = h1; l = l1; }
    else                      { src = s2; h = h2; l = l2; }
    float4 v = reinterpret_cast<const float4*>(src)[i];
    __nv_bfloat162 ha = pack_hi(v.x, v.y), hb = pack_hi(v.z, v.w);
    __nv_bfloat162 la = pack_lo(v.x, v.y, ha), lb = pack_lo(v.z, v.w, hb);
    uint2 hv = make_uint2(*(uint32_t*)&ha, *(uint32_t*)&hb);
    uint2 lv = make_uint2(*(uint32_t*)&la, *(uint32_t*)&lb);
    *reinterpret_cast<uint2*>(&h[(size_t)i * 4]) = hv;
    *reinterpret_cast<uint2*>(&l[(size_t)i * 4]) = lv;
}

// ---------------------------------------------------------------------------
// GEMM body: C[M,N] = (A[M,K] @ W[K,N] + bias) * scale, pre-split operands.
// BM=128 BN=128 BK=32, 256 threads, cp.async double-buffered,
// ONE __syncthreads per BK iteration. 3-term split MMA.
// ---------------------------------------------------------------------------
#define GAS 40
#define GBS 136
#define G_STG (128 * GAS * 2 + 32 * GBS * 2)
#define G_SMEM_BYTES (2 * G_STG * 2 + 512)

__device__ __forceinline__ void gemm_body(
    const __nv_bfloat16* __restrict__ Ahg, const __nv_bfloat16* __restrict__ Alg,
    const __nv_bfloat16* __restrict__ Bhg, const __nv_bfloat16* __restrict__ Blg,
    const float* __restrict__ bias,
    float* __restrict__ Cf, __nv_bfloat16* __restrict__ Ch, __nv_bfloat16* __restrict__ Cl,
    float scale, int N, int K, int bm0, int bn0, __nv_bfloat16* sm)
{
    float* biasS = (float*)(sm + 2 * G_STG);

    const int tid = threadIdx.x;
    const int lane = tid & 31;
    const int wid = tid >> 5;
    const int wm = wid >> 2;
    const int wn = wid & 3;

    if (tid < 128) biasS[tid] = bias[bn0 + tid];

    auto load_stage = [&](int s, int kt) {
        __nv_bfloat16* sAh = sm + s * G_STG;
        __nv_bfloat16* sAl = sAh + 128 * GAS;
        __nv_bfloat16* sBh = sAl + 128 * GAS;
        __nv_bfloat16* sBl = sBh + 32 * GBS;
        #pragma unroll
        for (int i = 0; i < 2; i++) {
            int idx = i * 256 + tid;
            int r = idx >> 2, cg = (idx & 3) * 8;
            cp16(smem_u32(&sAh[r * GAS + cg]), &Ahg[(size_t)(bm0 + r) * K + kt + cg]);
            cp16(smem_u32(&sAl[r * GAS + cg]), &Alg[(size_t)(bm0 + r) * K + kt + cg]);
        }
        #pragma unroll
        for (int i = 0; i < 2; i++) {
            int idx = i * 256 + tid;
            int r = idx >> 4, cg = (idx & 15) * 8;
            cp16(smem_u32(&sBh[r * GBS + cg]), &Bhg[(size_t)(kt + r) * N + bn0 + cg]);
            cp16(smem_u32(&sBl[r * GBS + cg]), &Blg[(size_t)(kt + r) * N + bn0 + cg]);
        }
    };

    float acc[4][4][4] = {};
    const int nk = K >> 5;

    load_stage(0, 0);
    CP_COMMIT();

    for (int it = 0; it < nk; it++) {
        CP_WAIT0();
        __syncthreads();
        if (it + 1 < nk) {
            load_stage((it + 1) & 1, (it + 1) * 32);
            CP_COMMIT();
        }

        const __nv_bfloat16* sAh = sm + (it & 1) * G_STG;
        const __nv_bfloat16* sAl = sAh + 128 * GAS;
        const __nv_bfloat16* sBh = sAl + 128 * GAS;
        const __nv_bfloat16* sBl = sBh + 32 * GBS;

        #pragma unroll
        for (int ks = 0; ks < 2; ks++) {
            uint32_t ah[4][4], al[4][4];
            #pragma unroll
            for (int mt = 0; mt < 4; mt++) {
                int r = wm * 64 + mt * 16 + (lane & 15);
                int c = ks * 16 + (lane >> 4) * 8;
                ldsm_x4(ah[mt], smem_u32(&sAh[r * GAS + c]));
                ldsm_x4(al[mt], smem_u32(&sAl[r * GAS + c]));
            }
            uint32_t bh[4][2], bl[4][2];
            #pragma unroll
            for (int p = 0; p < 2; p++) {
                int r = ks * 16 + (lane & 15);
                int c = wn * 32 + p * 16 + (lane >> 4) * 8;
                uint32_t t4[4];
                ldsm_x4t(t4, smem_u32(&sBh[r * GBS + c]));
                bh[2*p][0] = t4[0]; bh[2*p][1] = t4[1];
                bh[2*p+1][0] = t4[2]; bh[2*p+1][1] = t4[3];
                ldsm_x4t(t4, smem_u32(&sBl[r * GBS + c]));
                bl[2*p][0] = t4[0]; bl[2*p][1] = t4[1];
                bl[2*p+1][0] = t4[2]; bl[2*p+1][1] = t4[3];
            }
            #pragma unroll
            for (int mt = 0; mt < 4; mt++)
                #pragma unroll
                for (int nt = 0; nt < 4; nt++) {
                    mma16816(acc[mt][nt], ah[mt], bh[nt]);
                    mma16816(acc[mt][nt], ah[mt], bl[nt]);
                    mma16816(acc[mt][nt], al[mt], bh[nt]);
                }
        }
    }

    #pragma unroll
    for (int mt = 0; mt < 4; mt++)
        #pragma unroll
        for (int nt = 0; nt < 4; nt++) {
            int row = bm0 + wm * 64 + mt * 16 + (lane >> 2);
            int colL = wn * 32 + nt * 8 + (lane & 3) * 2;
            int col = bn0 + colL;
            float b0 = biasS[colL], b1 = biasS[colL + 1];
            float v00 = (acc[mt][nt][0] + b0) * scale;
            float v01 = (acc[mt][nt][1] + b1) * scale;
            float v10 = (acc[mt][nt][2] + b0) * scale;
            float v11 = (acc[mt][nt][3] + b1) * scale;
            if (Cf) {
                *reinterpret_cast<float2*>(&Cf[(size_t)row * N + col]) = make_float2(v00, v01);
                *reinterpret_cast<float2*>(&Cf[(size_t)(row + 8) * N + col]) = make_float2(v10, v11);
            } else {
                __nv_bfloat162 h0 = pack_hi(v00, v01), l0 = pack_lo(v00, v01, h0);
                *reinterpret_cast<__nv_bfloat162*>(&Ch[(size_t)row * N + col]) = h0;
                *reinterpret_cast<__nv_bfloat162*>(&Cl[(size_t)row * N + col]) = l0;
                __nv_bfloat162 h1 = pack_hi(v10, v11), l1 = pack_lo(v10, v11, h1);
                *reinterpret_cast<__nv_bfloat162*>(&Ch[(size_t)(row + 8) * N + col]) = h1;
                *reinterpret_cast<__nv_bfloat162*>(&Cl[(size_t)(row + 8) * N + col]) = l1;
            }
        }
}

// ---------------------------------------------------------------------------
// Fused Q/K/V projections: 768 CTAs in one launch.
//   id < 512        : Q tile  (16 n-tiles x 32 m-tiles), scaled by 1/sqrt(dk)
//   512 <= id < 640 : K tile  (4 x 32)
//   640 <= id < 768 : V tile  (4 x 32)
// ---------------------------------------------------------------------------
__global__ __launch_bounds__(256) void gemm_qkv_kernel(
    const __nv_bfloat16* __restrict__ qh, const __nv_bfloat16* __restrict__ ql,
    const __nv_bfloat16* __restrict__ Wqh, const __nv_bfloat16* __restrict__ Wql,
    const float* __restrict__ bq,
    __nv_bfloat16* __restrict__ Qh, __nv_bfloat16* __restrict__ Ql_,
    const __nv_bfloat16* __restrict__ kh, const __nv_bfloat16* __restrict__ kl,
    const __nv_bfloat16* __restrict__ Wkh, const __nv_bfloat16* __restrict__ Wkl,
    const float* __restrict__ bk,
    __nv_bfloat16* __restrict__ Kh, __nv_bfloat16* __restrict__ Kl,
    const __nv_bfloat16* __restrict__ vh, const __nv_bfloat16* __restrict__ vl,
    const __nv_bfloat16* __restrict__ Wvh, const __nv_bfloat16* __restrict__ Wvl,
    const float* __restrict__ bv,
    __nv_bfloat16* __restrict__ Vh, __nv_bfloat16* __restrict__ Vl,
    float qscale)
{
    extern __shared__ __nv_bfloat16 sm[];
    const int id = blockIdx.x;
    if (id < 512) {
        gemm_body(qh, ql, Wqh, Wql, bq, nullptr, Qh, Ql_, qscale, DIM, DIM,
                  (id >> 4) * 128, (id & 15) * 128, sm);
    } else if (id < 640) {
        int t = id - 512;
        gemm_body(kh, kl, Wkh, Wkl, bk, nullptr, Kh, Kl, 1.f, KVDIM, DIM,
                  (t >> 2) * 128, (t & 3) * 128, sm);
    } else {
        int t = id - 640;
        gemm_body(vh, vl, Wvh, Wvl, bv, nullptr, Vh, Vl, 1.f, KVDIM, DIM,
                  (t >> 2) * 128, (t & 3) * 128, sm);
    }
}

// ---------------------------------------------------------------------------
// Fused Wo projection + AW normalize: 512 gemm CTAs + 1024 normalize CTAs.
// Normalize CTAs soak idle DRAM bandwidth under the tensor-bound gemm.
// ---------------------------------------------------------------------------
#define NORM_CTAS 1024

__global__ __launch_bounds__(256) void gemm_wo_norm_kernel(
    const __nv_bfloat16* __restrict__ Oh, const __nv_bfloat16* __restrict__ Ol,
    const __nv_bfloat16* __restrict__ Woh, const __nv_bfloat16* __restrict__ Wol,
    const float* __restrict__ bo, float* __restrict__ out,
    float* __restrict__ AW, const float* __restrict__ invL)
{
    extern __shared__ __nv_bfloat16 sm[];
    const int id = blockIdx.x;
    if (id < 512) {
        gemm_body(Oh, Ol, Woh, Wol, bo, out, nullptr, nullptr, 1.f, DIM, DIM,
                  (id >> 4) * 128, (id & 15) * 128, sm);
    } else {
        const size_t nf4 = (size_t)32 * T * T / 4;          // 33,554,432 float4
        const size_t stride = (size_t)NORM_CTAS * 256;
        for (size_t i4 = (size_t)(id - 512) * 256 + threadIdx.x; i4 < nf4; i4 += stride) {
            int row = (int)((i4 * 4) >> 11);
            float il = __ldg(&invL[row]);
            float4 v = reinterpret_cast<float4*>(AW)[i4];
            v.x *= il; v.y *= il; v.z *= il; v.w *= il;
            reinterpret_cast<float4*>(AW)[i4] = v;
        }
    }
}

// ---------------------------------------------------------------------------
// Attention (single pass): grid (32 qtiles x 32 bh), 256 threads (8 warps 4x2).
// 32-key double-buffered KV tiles; total smem 115.2KB => 2 CTAs/SM.
// ---------------------------------------------------------------------------
#define AAS 136
#define APS 40
#define AT_Q   0
#define AT_KV  (2 * 64 * AAS)
#define AT_KVS (4 * 32 * AAS)
#define AT_P   (AT_KV + 2 * AT_KVS)
#define AT_LP  (AT_P + 2 * 64 * APS)
#define ATTN_SMEM_BYTES (AT_LP * 2 + 512)

__global__ __launch_bounds__(256, 2) void attn_kernel(
    const __nv_bfloat16* __restrict__ Qhg, const __nv_bfloat16* __restrict__ Qlg,
    const __nv_bfloat16* __restrict__ Khg, const __nv_bfloat16* __restrict__ Klg,
    const __nv_bfloat16* __restrict__ Vhg, const __nv_bfloat16* __restrict__ Vlg,
    float* __restrict__ AW, float* __restrict__ invLg,
    __nv_bfloat16* __restrict__ Ohg, __nv_bfloat16* __restrict__ Olg)
{
    extern __shared__ __nv_bfloat16 sm[];
    __nv_bfloat16* Qh = sm + AT_Q;
    __nv_bfloat16* Ql = Qh + 64 * AAS;
    __nv_bfloat16* Ph = sm + AT_P;
    __nv_bfloat16* Pl = Ph + 64 * APS;
    float* lp = (float*)(sm + AT_LP);

    const int tid = threadIdx.x;
    const int lane = tid & 31;
    const int wid = tid >> 5;
    const int wr = wid & 3;
    const int wc = wid >> 2;
    const int qt = blockIdx.x;
    const int bh = blockIdx.y;
    const int b = bh >> 4, h = bh & 15, kv = h >> 2;

    const size_t qrow0 = (size_t)b * T + qt * 64;
    const size_t krow0 = (size_t)b * T;
    const int kcol = kv * 128;

    auto load_kv = [&](int s, size_t row0) {
        __nv_bfloat16* base = sm + AT_KV + s * AT_KVS;
        #pragma unroll
        for (int i = 0; i < 2; i++) {
            int idx = i * 256 + tid;
            int r = idx >> 4, cg = (idx & 15) * 8;
            cp16(smem_u32(&base[r * AAS + cg]),            &Khg[(row0 + r) * KVDIM + kcol + cg]);
            cp16(smem_u32(&base[32*AAS + r * AAS + cg]),   &Klg[(row0 + r) * KVDIM + kcol + cg]);
            cp16(smem_u32(&base[2*32*AAS + r * AAS + cg]), &Vhg[(row0 + r) * KVDIM + kcol + cg]);
            cp16(smem_u32(&base[3*32*AAS + r * AAS + cg]), &Vlg[(row0 + r) * KVDIM + kcol + cg]);
        }
    };

    load_kv(0, krow0);
    CP_COMMIT();
    #pragma unroll
    for (int i = 0; i < 4; i++) {
        int idx = i * 256 + tid;
        int r = idx >> 4, cg = (idx & 15) * 8;
        *reinterpret_cast<uint4*>(&Qh[r * AAS + cg]) =
            *reinterpret_cast<const uint4*>(&Qhg[(qrow0 + r) * DIM + h * 128 + cg]);
        *reinterpret_cast<uint4*>(&Ql[r * AAS + cg]) =
            *reinterpret_cast<const uint4*>(&Qlg[(qrow0 + r) * DIM + h * 128 + cg]);
    }

    float l0 = 0.f, l1 = 0.f;
    float o[8][4] = {};

    const int r0 = wr * 16 + (lane >> 2);
    const int c0 = (lane & 3) * 2;
    const size_t gb = ((size_t)bh * T + (size_t)qt * 64) * T;

    #pragma unroll 1
    for (int kt = 0; kt < 64; kt++) {
        CP_WAIT0();
        __syncthreads();
        if (kt < 63) {
            load_kv((kt + 1) & 1, krow0 + (kt + 1) * 32);
            CP_COMMIT();
        }

        const __nv_bfloat16* Kbh = sm + AT_KV + (kt & 1) * AT_KVS;
        const __nv_bfloat16* Kbl = Kbh + 32 * AAS;
        const __nv_bfloat16* Vbh = Kbh + 2 * 32 * AAS;
        const __nv_bfloat16* Vbl = Kbh + 3 * 32 * AAS;

        float s[2][4];
        #pragma unroll
        for (int nt = 0; nt < 2; nt++)
            #pragma unroll
            for (int j = 0; j < 4; j++) s[nt][j] = 0.f;

        #pragma unroll
        for (int kk = 0; kk < 8; kk++) {
            uint32_t ah[4], al[4];
            int ar = wr * 16 + (lane & 15), ac = kk * 16 + (lane >> 4) * 8;
            ldsm_x4(ah, smem_u32(&Qh[ar * AAS + ac]));
            ldsm_x4(al, smem_u32(&Ql[ar * AAS + ac]));
            int br = wc * 16 + (lane & 15), bc = kk * 16 + (lane >> 4) * 8;
            uint32_t b4h[4], b4l[4];
            ldsm_x4(b4h, smem_u32(&Kbh[br * AAS + bc]));
            ldsm_x4(b4l, smem_u32(&Kbl[br * AAS + bc]));
            uint32_t be_h[2] = {b4h[0], b4h[2]}, bo_h[2] = {b4h[1], b4h[3]};
            uint32_t be_l[2] = {b4l[0], b4l[2]}, bo_l[2] = {b4l[1], b4l[3]};
            mma16816(s[0], ah, be_h); mma16816(s[0], ah, be_l); mma16816(s[0], al, be_h);
            mma16816(s[1], ah, bo_h); mma16816(s[1], ah, bo_l); mma16816(s[1], al, bo_h);
        }

        #pragma unroll
        for (int nt = 0; nt < 2; nt++) {
            s[nt][0] = __expf(s[nt][0]); s[nt][1] = __expf(s[nt][1]);
            s[nt][2] = __expf(s[nt][2]); s[nt][3] = __expf(s[nt][3]);
            l0 += s[nt][0] + s[nt][1];
            l1 += s[nt][2] + s[nt][3];
            int colL = wc * 16 + nt * 8 + c0;
            __nv_bfloat162 h0 = pack_hi(s[nt][0], s[nt][1]), lo0 = pack_lo(s[nt][0], s[nt][1], h0);
            __nv_bfloat162 h1 = pack_hi(s[nt][2], s[nt][3]), lo1 = pack_lo(s[nt][2], s[nt][3], h1);
            *reinterpret_cast<__nv_bfloat162*>(&Ph[r0 * APS + colL]) = h0;
            *reinterpret_cast<__nv_bfloat162*>(&Pl[r0 * APS + colL]) = lo0;
            *reinterpret_cast<__nv_bfloat162*>(&Ph[(r0 + 8) * APS + colL]) = h1;
            *reinterpret_cast<__nv_bfloat162*>(&Pl[(r0 + 8) * APS + colL]) = lo1;
        }
        __syncthreads();

        #pragma unroll
        for (int kc = 0; kc < 2; kc++) {
            uint32_t ph4[4], pl4[4];
            int pr = wr * 16 + (lane & 15), pc = kc * 16 + (lane >> 4) * 8;
            ldsm_x4(ph4, smem_u32(&Ph[pr * APS + pc]));
            ldsm_x4(pl4, smem_u32(&Pl[pr * APS + pc]));
            #pragma unroll
            for (int p = 0; p < 4; p++) {
                int vr = kc * 16 + (lane & 15);
                int vc = wc * 64 + p * 16 + (lane >> 4) * 8;
                uint32_t v4h[4], v4l[4];
                ldsm_x4t(v4h, smem_u32(&Vbh[vr * AAS + vc]));
                ldsm_x4t(v4l, smem_u32(&Vbl[vr * AAS + vc]));
                uint32_t be_h[2] = {v4h[0], v4h[1]}, bo_h[2] = {v4h[2], v4h[3]};
                uint32_t be_l[2] = {v4l[0], v4l[1]}, bo_l[2] = {v4l[2], v4l[3]};
                mma16816(o[2*p],   ph4, be_h); mma16816(o[2*p],   ph4, be_l); mma16816(o[2*p],   pl4, be_h);
                mma16816(o[2*p+1], ph4, bo_h); mma16816(o[2*p+1], ph4, bo_l); mma16816(o[2*p+1], pl4, bo_h);
            }
        }

        #pragma unroll
        for (int nt = 0; nt < 2; nt++) {
            int col = kt * 32 + wc * 16 + nt * 8 + c0;
            *reinterpret_cast<float2*>(&AW[gb + (size_t)r0 * T + col]) =
                make_float2(s[nt][0], s[nt][1]);
            *reinterpret_cast<float2*>(&AW[gb + (size_t)(r0 + 8) * T + col]) =
                make_float2(s[nt][2], s[nt][3]);
        }
    }

    l0 += __shfl_xor_sync(0xffffffffu, l0, 1);
    l0 += __shfl_xor_sync(0xffffffffu, l0, 2);
    l1 += __shfl_xor_sync(0xffffffffu, l1, 1);
    l1 += __shfl_xor_sync(0xffffffffu, l1, 2);
    __syncthreads();
    if ((lane & 3) == 0) {
        lp[wc * 64 + r0] = l0;
        lp[wc * 64 + r0 + 8] = l1;
    }
    __syncthreads();

    if (tid < 64) {
        float il = 1.f / (lp[tid] + lp[64 + tid]);
        invLg[(size_t)bh * T + qt * 64 + tid] = il;
    }

    const float ilA = 1.f / (lp[r0] + lp[64 + r0]);
    const float ilB = 1.f / (lp[r0 + 8] + lp[64 + r0 + 8]);

    #pragma unroll
    for (int nt = 0; nt < 8; nt++) {
        int c = h * 128 + wc * 64 + nt * 8 + c0;
        float v00 = o[nt][0] * ilA, v01 = o[nt][1] * ilA;
        float v10 = o[nt][2] * ilB, v11 = o[nt][3] * ilB;
        __nv_bfloat162 h0 = pack_hi(v00, v01), l0v = pack_lo(v00, v01, h0);
        __nv_bfloat162 h1 = pack_hi(v10, v11), l1v = pack_lo(v10, v11, h1);
        *reinterpret_cast<__nv_bfloat162*>(&Ohg[(qrow0 + r0) * DIM + c]) = h0;
        *reinterpret_cast<__nv_bfloat162*>(&Olg[(qrow0 + r0) * DIM + c]) = l0v;
        *reinterpret_cast<__nv_bfloat162*>(&Ohg[(qrow0 + r0 + 8) * DIM + c]) = h1;
        *reinterpret_cast<__nv_bfloat162*>(&Olg[(qrow0 + r0 + 8) * DIM + c]) = l1v;
    }
}

// ---------------------------------------------------------------------------
// launch
// ---------------------------------------------------------------------------
extern "C" void kernel_launch(void* const* d_in, const int* in_sizes, int n_in,
                              void* d_out, int out_size)
{
    const float* q  = (const float*)d_in[0];
    const float* k  = (const float*)d_in[1];
    const float* v  = (const float*)d_in[2];
    const float* Wq = (const float*)d_in[3];
    const float* bq = (const float*)d_in[4];
    const float* Wk = (const float*)d_in[5];
    const float* bk = (const float*)d_in[6];
    const float* Wv = (const float*)d_in[7];
    const float* bv = (const float*)d_in[8];
    const float* Wo = (const float*)d_in[9];
    const float* bo = (const float*)d_in[10];

    float* out   = (float*)d_out;
    float* attnW = out + (size_t)BT * DIM;

    __nv_bfloat16 *qh, *ql, *kh, *kl, *vh, *vl;
    __nv_bfloat16 *Wqh, *Wql, *Wkh, *Wkl, *Wvh, *Wvl, *Woh, *Wol;
    __nv_bfloat16 *Qh, *Ql, *Kh, *Kl, *Vh, *Vl, *Oh, *Ol;
    float* invL;
    cudaGetSymbolAddress((void**)&qh, g_qh);   cudaGetSymbolAddress((void**)&ql, g_ql);
    cudaGetSymbolAddress((void**)&kh, g_kh);   cudaGetSymbolAddress((void**)&kl, g_kl);
    cudaGetSymbolAddress((void**)&vh, g_vh);   cudaGetSymbolAddress((void**)&vl, g_vl);
    cudaGetSymbolAddress((void**)&Wqh, g_Wqh); cudaGetSymbolAddress((void**)&Wql, g_Wql);
    cudaGetSymbolAddress((void**)&Wkh, g_Wkh); cudaGetSymbolAddress((void**)&Wkl, g_Wkl);
    cudaGetSymbolAddress((void**)&Wvh, g_Wvh); cudaGetSymbolAddress((void**)&Wvl, g_Wvl);
    cudaGetSymbolAddress((void**)&Woh, g_Woh); cudaGetSymbolAddress((void**)&Wol, g_Wol);
    cudaGetSymbolAddress((void**)&Qh, g_Qh);   cudaGetSymbolAddress((void**)&Ql, g_Ql);
    cudaGetSymbolAddress((void**)&Kh, g_Kh);   cudaGetSymbolAddress((void**)&Kl, g_Kl);
    cudaGetSymbolAddress((void**)&Vh, g_Vh);   cudaGetSymbolAddress((void**)&Vl, g_Vl);
    cudaGetSymbolAddress((void**)&Oh, g_Oh);   cudaGetSymbolAddress((void**)&Ol, g_Ol);
    cudaGetSymbolAddress((void**)&invL, g_invL);

    cudaFuncSetAttribute(gemm_qkv_kernel, cudaFuncAttributeMaxDynamicSharedMemorySize,
                         G_SMEM_BYTES);
    cudaFuncSetAttribute(gemm_wo_norm_kernel, cudaFuncAttributeMaxDynamicSharedMemorySize,
                         G_SMEM_BYTES);
    cudaFuncSetAttribute(attn_kernel, cudaFuncAttributeMaxDynamicSharedMemorySize,
                         ATTN_SMEM_BYTES);

    const float scale = 0.08838834764831845f;  // 1/sqrt(128)

    // splits (fp32 -> bf16 hi/lo): 3 fused launches
    const int nBD = BT * DIM / 4, nDD = DIM * DIM / 4, nDK = DIM * KVDIM / 4;
    split3_kernel<<<dim3((nBD + 255) / 256, 3), 256>>>(
        q, qh, ql, k, kh, kl, v, vh, vl, nBD);
    split3_kernel<<<dim3((nDD + 255) / 256, 2), 256>>>(
        Wq, Wqh, Wql, Wo, Woh, Wol, nullptr, nullptr, nullptr, nDD);
    split3_kernel<<<dim3((nDK + 255) / 256, 2), 256>>>(
        Wk, Wkh, Wkl, Wv, Wvh, Wvl, nullptr, nullptr, nullptr, nDK);

    // fused Q/K/V projections (one launch, one wave tail)
    gemm_qkv_kernel<<<768, 256, G_SMEM_BYTES>>>(
        qh, ql, Wqh, Wql, bq, Qh, Ql,
        kh, kl, Wkh, Wkl, bk, Kh, Kl,
        vh, vl, Wvh, Wvl, bv, Vh, Vl,
        scale);

    // attention (raw exp -> AW, O pre-split & scaled)
    attn_kernel<<<dim3(T / 64, 32), 256, ATTN_SMEM_BYTES>>>(
        Qh, Ql, Kh, Kl, Vh, Vl, attnW, invL, Oh, Ol);

    // fused Wo projection + AW normalize (memory-bound CTAs soak idle HBM)
    gemm_wo_norm_kernel<<<512 + NORM_CTAS, 256, G_SMEM_BYTES>>>(
        Oh, Ol, Woh, Wol, bo, out, attnW, invL);
}

// round 11
// speedup vs baseline: 1.0010x; 1.0010x over previous
#include <cuda_runtime.h>
#include <cuda_bf16.h>
#include <cstdint>
#include <cmath>

// ---------------------------------------------------------------------------
// GroupedQueryAttention: B=2, T=2048, DIM=2048, H=16, KH=4, DK=DV=128
// d_out = [ out (2,2048,2048) fp32 | attn_weight (2,16,2048,2048) fp32 ]
//
// Round 7: kernel fusion for pipe overlap —
//   * Q/K/V projections in ONE launch (one wave tail)
//   * Wo projection + AW normalize in ONE launch (normalize soaks idle HBM
//     under the tensor-bound gemm)
//   * GEMM mainloop: single __syncthreads per BK iteration
// Attention unchanged from round 6. Split-bf16 3-term numerics everywhere.
// ---------------------------------------------------------------------------

#define BT 4096
#define DIM 2048
#define KVDIM 512
#define T 2048

// ---- device scratch (no allocation allowed) ----
__device__ __nv_bfloat16 g_qh[BT * DIM],  g_ql[BT * DIM];
__device__ __nv_bfloat16 g_kh[BT * DIM],  g_kl[BT * DIM];
__device__ __nv_bfloat16 g_vh[BT * DIM],  g_vl[BT * DIM];
__device__ __nv_bfloat16 g_Wqh[DIM * DIM], g_Wql[DIM * DIM];
__device__ __nv_bfloat16 g_Wkh[DIM * KVDIM], g_Wkl[DIM * KVDIM];
__device__ __nv_bfloat16 g_Wvh[DIM * KVDIM], g_Wvl[DIM * KVDIM];
__device__ __nv_bfloat16 g_Woh[DIM * DIM], g_Wol[DIM * DIM];
__device__ __nv_bfloat16 g_Qh[BT * DIM],  g_Ql[BT * DIM];
__device__ __nv_bfloat16 g_Kh[BT * KVDIM], g_Kl[BT * KVDIM];
__device__ __nv_bfloat16 g_Vh[BT * KVDIM], g_Vl[BT * KVDIM];
__device__ __nv_bfloat16 g_Oh[BT * DIM],  g_Ol[BT * DIM];
__device__ float g_invL[32 * T];

// ---------------------------------------------------------------------------
// helpers
// ---------------------------------------------------------------------------
__device__ __forceinline__ uint32_t smem_u32(const void* p) {
    return (uint32_t)__cvta_generic_to_shared(p);
}
__device__ __forceinline__ void ldsm_x4(uint32_t* r, uint32_t addr) {
    asm volatile("ldmatrix.sync.aligned.m8n8.x4.shared.b16 {%0,%1,%2,%3}, [%4];"
                 : "=r"(r[0]), "=r"(r[1]), "=r"(r[2]), "=r"(r[3]) : "r"(addr));
}
__device__ __forceinline__ void ldsm_x4t(uint32_t* r, uint32_t addr) {
    asm volatile("ldmatrix.sync.aligned.m8n8.x4.trans.shared.b16 {%0,%1,%2,%3}, [%4];"
                 : "=r"(r[0]), "=r"(r[1]), "=r"(r[2]), "=r"(r[3]) : "r"(addr));
}
__device__ __forceinline__ void mma16816(float* c, const uint32_t* a, const uint32_t* b) {
    asm volatile(
        "mma.sync.aligned.m16n8k16.row.col.f32.bf16.bf16.f32 "
        "{%0,%1,%2,%3}, {%4,%5,%6,%7}, {%8,%9}, {%0,%1,%2,%3};\n"
        : "+f"(c[0]), "+f"(c[1]), "+f"(c[2]), "+f"(c[3])
        : "r"(a[0]), "r"(a[1]), "r"(a[2]), "r"(a[3]), "r"(b[0]), "r"(b[1]));
}
__device__ __forceinline__ void cp16(uint32_t saddr, const void* g) {
    asm volatile("cp.async.cg.shared.global [%0], [%1], 16;" :: "r"(saddr), "l"(g));
}
#define CP_COMMIT() asm volatile("cp.async.commit_group;")
#define CP_WAIT0()  asm volatile("cp.async.wait_group 0;")

__device__ __forceinline__ __nv_bfloat162 pack_hi(float a, float b) {
    __nv_bfloat162 r; r.x = __float2bfloat16(a); r.y = __float2bfloat16(b); return r;
}
__device__ __forceinline__ __nv_bfloat162 pack_lo(float a, float b, __nv_bfloat162 h) {
    __nv_bfloat162 r;
    r.x = __float2bfloat16(a - __bfloat162float(h.x));
    r.y = __float2bfloat16(b - __bfloat162float(h.y));
    return r;
}

// ---------------------------------------------------------------------------
// split: fp32 -> bf16 hi/lo; blockIdx.y selects one of up to 3 tensors
// ---------------------------------------------------------------------------
__global__ void split3_kernel(
    const float* __restrict__ s0, __nv_bfloat16* __restrict__ h0, __nv_bfloat16* __restrict__ l0,
    const float* __restrict__ s1, __nv_bfloat16* __restrict__ h1, __nv_bfloat16* __restrict__ l1,
    const float* __restrict__ s2, __nv_bfloat16* __restrict__ h2, __nv_bfloat16* __restrict__ l2,
    int n4)
{
    int i = blockIdx.x * blockDim.x + threadIdx.x;
    if (i >= n4) return;
    const float* src; __nv_bfloat16 *h, *l;
    if (blockIdx.y == 0)      { src = s0; h = h0; l = l0; }
    else if (blockIdx.y == 1) { src = s1; h = h1; l = l1; }
    else                      { src = s2; h = h2; l = l2; }
    float4 v = reinterpret_cast<const float4*>(src)[i];
    __nv_bfloat162 ha = pack_hi(v.x, v.y), hb = pack_hi(v.z, v.w);
    __nv_bfloat162 la = pack_lo(v.x, v.y, ha), lb = pack_lo(v.z, v.w, hb);
    uint2 hv = make_uint2(*(uint32_t*)&ha, *(uint32_t*)&hb);
    uint2 lv = make_uint2(*(uint32_t*)&la, *(uint32_t*)&lb);
    *reinterpret_cast<uint2*>(&h[(size_t)i * 4]) = hv;
    *reinterpret_cast<uint2*>(&l[(size_t)i * 4]) = lv;
}

// ---------------------------------------------------------------------------
// GEMM body: C[M,N] = (A[M,K] @ W[K,N] + bias) * scale, pre-split operands.
// BM=128 BN=128 BK=32, 256 threads, cp.async double-buffered,
// ONE __syncthreads per BK iteration. 3-term split MMA.
// ---------------------------------------------------------------------------
#define GAS 40
#define GBS 136
#define G_STG (128 * GAS * 2 + 32 * GBS * 2)
#define G_SMEM_BYTES (2 * G_STG * 2 + 512)

__device__ __forceinline__ void gemm_body(
    const __nv_bfloat16* __restrict__ Ahg, const __nv_bfloat16* __restrict__ Alg,
    const __nv_bfloat16* __restrict__ Bhg, const __nv_bfloat16* __restrict__ Blg,
    const float* __restrict__ bias,
    float* __restrict__ Cf, __nv_bfloat16* __restrict__ Ch, __nv_bfloat16* __restrict__ Cl,
    float scale, int N, int K, int bm0, int bn0, __nv_bfloat16* sm)
{
    float* biasS = (float*)(sm + 2 * G_STG);

    const int tid = threadIdx.x;
    const int lane = tid & 31;
    const int wid = tid >> 5;
    const int wm = wid >> 2;
    const int wn = wid & 3;

    if (tid < 128) biasS[tid] = bias[bn0 + tid];

    auto load_stage = [&](int s, int kt) {
        __nv_bfloat16* sAh = sm + s * G_STG;
        __nv_bfloat16* sAl = sAh + 128 * GAS;
        __nv_bfloat16* sBh = sAl + 128 * GAS;
        __nv_bfloat16* sBl = sBh + 32 * GBS;
        #pragma unroll
        for (int i = 0; i < 2; i++) {
            int idx = i * 256 + tid;
            int r = idx >> 2, cg = (idx & 3) * 8;
            cp16(smem_u32(&sAh[r * GAS + cg]), &Ahg[(size_t)(bm0 + r) * K + kt + cg]);
            cp16(smem_u32(&sAl[r * GAS + cg]), &Alg[(size_t)(bm0 + r) * K + kt + cg]);
        }
        #pragma unroll
        for (int i = 0; i < 2; i++) {
            int idx = i * 256 + tid;
            int r = idx >> 4, cg = (idx & 15) * 8;
            cp16(smem_u32(&sBh[r * GBS + cg]), &Bhg[(size_t)(kt + r) * N + bn0 + cg]);
            cp16(smem_u32(&sBl[r * GBS + cg]), &Blg[(size_t)(kt + r) * N + bn0 + cg]);
        }
    };

    float acc[4][4][4] = {};
    const int nk = K >> 5;

    load_stage(0, 0);
    CP_COMMIT();

    for (int it = 0; it < nk; it++) {
        CP_WAIT0();
        __syncthreads();
        if (it + 1 < nk) {
            load_stage((it + 1) & 1, (it + 1) * 32);
            CP_COMMIT();
        }

        const __nv_bfloat16* sAh = sm + (it & 1) * G_STG;
        const __nv_bfloat16* sAl = sAh + 128 * GAS;
        const __nv_bfloat16* sBh = sAl + 128 * GAS;
        const __nv_bfloat16* sBl = sBh + 32 * GBS;

        #pragma unroll
        for (int ks = 0; ks < 2; ks++) {
            uint32_t ah[4][4], al[4][4];
            #pragma unroll
            for (int mt = 0; mt < 4; mt++) {
                int r = wm * 64 + mt * 16 + (lane & 15);
                int c = ks * 16 + (lane >> 4) * 8;
                ldsm_x4(ah[mt], smem_u32(&sAh[r * GAS + c]));
                ldsm_x4(al[mt], smem_u32(&sAl[r * GAS + c]));
            }
            uint32_t bh[4][2], bl[4][2];
            #pragma unroll
            for (int p = 0; p < 2; p++) {
                int r = ks * 16 + (lane & 15);
                int c = wn * 32 + p * 16 + (lane >> 4) * 8;
                uint32_t t4[4];
                ldsm_x4t(t4, smem_u32(&sBh[r * GBS + c]));
                bh[2*p][0] = t4[0]; bh[2*p][1] = t4[1];
                bh[2*p+1][0] = t4[2]; bh[2*p+1][1] = t4[3];
                ldsm_x4t(t4, smem_u32(&sBl[r * GBS + c]));
                bl[2*p][0] = t4[0]; bl[2*p][1] = t4[1];
                bl[2*p+1][0] = t4[2]; bl[2*p+1][1] = t4[3];
            }
            #pragma unroll
            for (int mt = 0; mt < 4; mt++)
                #pragma unroll
                for (int nt = 0; nt < 4; nt++) {
                    mma16816(acc[mt][nt], ah[mt], bh[nt]);
                    mma16816(acc[mt][nt], ah[mt], bl[nt]);
                    mma16816(acc[mt][nt], al[mt], bh[nt]);
                }
        }
    }

    #pragma unroll
    for (int mt = 0; mt < 4; mt++)
        #pragma unroll
        for (int nt = 0; nt < 4; nt++) {
            int row = bm0 + wm * 64 + mt * 16 + (lane >> 2);
            int colL = wn * 32 + nt * 8 + (lane & 3) * 2;
            int col = bn0 + colL;
            float b0 = biasS[colL], b1 = biasS[colL + 1];
            float v00 = (acc[mt][nt][0] + b0) * scale;
            float v01 = (acc[mt][nt][1] + b1) * scale;
            float v10 = (acc[mt][nt][2] + b0) * scale;
            float v11 = (acc[mt][nt][3] + b1) * scale;
            if (Cf) {
                *reinterpret_cast<float2*>(&Cf[(size_t)row * N + col]) = make_float2(v00, v01);
                *reinterpret_cast<float2*>(&Cf[(size_t)(row + 8) * N + col]) = make_float2(v10, v11);
            } else {
                __nv_bfloat162 h0 = pack_hi(v00, v01), l0 = pack_lo(v00, v01, h0);
                *reinterpret_cast<__nv_bfloat162*>(&Ch[(size_t)row * N + col]) = h0;
                *reinterpret_cast<__nv_bfloat162*>(&Cl[(size_t)row * N + col]) = l0;
                __nv_bfloat162 h1 = pack_hi(v10, v11), l1 = pack_lo(v10, v11, h1);
                *reinterpret_cast<__nv_bfloat162*>(&Ch[(size_t)(row + 8) * N + col]) = h1;
                *reinterpret_cast<__nv_bfloat162*>(&Cl[(size_t)(row + 8) * N + col]) = l1;
            }
        }
}

// ---------------------------------------------------------------------------
// Fused Q/K/V projections: 768 CTAs in one launch.
//   id < 512        : Q tile  (16 n-tiles x 32 m-tiles), scaled by 1/sqrt(dk)
//   512 <= id < 640 : K tile  (4 x 32)
//   640 <= id < 768 : V tile  (4 x 32)
// ---------------------------------------------------------------------------
__global__ __launch_bounds__(256) void gemm_qkv_kernel(
    const __nv_bfloat16* __restrict__ qh, const __nv_bfloat16* __restrict__ ql,
    const __nv_bfloat16* __restrict__ Wqh, const __nv_bfloat16* __restrict__ Wql,
    const float* __restrict__ bq,
    __nv_bfloat16* __restrict__ Qh, __nv_bfloat16* __restrict__ Ql_,
    const __nv_bfloat16* __restrict__ kh, const __nv_bfloat16* __restrict__ kl,
    const __nv_bfloat16* __restrict__ Wkh, const __nv_bfloat16* __restrict__ Wkl,
    const float* __restrict__ bk,
    __nv_bfloat16* __restrict__ Kh, __nv_bfloat16* __restrict__ Kl,
    const __nv_bfloat16* __restrict__ vh, const __nv_bfloat16* __restrict__ vl,
    const __nv_bfloat16* __restrict__ Wvh, const __nv_bfloat16* __restrict__ Wvl,
    const float* __restrict__ bv,
    __nv_bfloat16* __restrict__ Vh, __nv_bfloat16* __restrict__ Vl,
    float qscale)
{
    extern __shared__ __nv_bfloat16 sm[];
    const int id = blockIdx.x;
    if (id < 512) {
        gemm_body(qh, ql, Wqh, Wql, bq, nullptr, Qh, Ql_, qscale, DIM, DIM,
                  (id >> 4) * 128, (id & 15) * 128, sm);
    } else if (id < 640) {
        int t = id - 512;
        gemm_body(kh, kl, Wkh, Wkl, bk, nullptr, Kh, Kl, 1.f, KVDIM, DIM,
                  (t >> 2) * 128, (t & 3) * 128, sm);
    } else {
        int t = id - 640;
        gemm_body(vh, vl, Wvh, Wvl, bv, nullptr, Vh, Vl, 1.f, KVDIM, DIM,
                  (t >> 2) * 128, (t & 3) * 128, sm);
    }
}

// ---------------------------------------------------------------------------
// Fused Wo projection + AW normalize: 512 gemm CTAs + 1024 normalize CTAs.
// Normalize CTAs soak idle DRAM bandwidth under the tensor-bound gemm.
// ---------------------------------------------------------------------------
#define NORM_CTAS 1024

__global__ __launch_bounds__(256) void gemm_wo_norm_kernel(
    const __nv_bfloat16* __restrict__ Oh, const __nv_bfloat16* __restrict__ Ol,
    const __nv_bfloat16* __restrict__ Woh, const __nv_bfloat16* __restrict__ Wol,
    const float* __restrict__ bo, float* __restrict__ out,
    float* __restrict__ AW, const float* __restrict__ invL)
{
    extern __shared__ __nv_bfloat16 sm[];
    const int id = blockIdx.x;
    if (id < 512) {
        gemm_body(Oh, Ol, Woh, Wol, bo, out, nullptr, nullptr, 1.f, DIM, DIM,
                  (id >> 4) * 128, (id & 15) * 128, sm);
    } else {
        const size_t nf4 = (size_t)32 * T * T / 4;          // 33,554,432 float4
        const size_t stride = (size_t)NORM_CTAS * 256;
        for (size_t i4 = (size_t)(id - 512) * 256 + threadIdx.x; i4 < nf4; i4 += stride) {
            int row = (int)((i4 * 4) >> 11);
            float il = __ldg(&invL[row]);
            float4 v = reinterpret_cast<float4*>(AW)[i4];
            v.x *= il; v.y *= il; v.z *= il; v.w *= il;
            reinterpret_cast<float4*>(AW)[i4] = v;
        }
    }
}

// ---------------------------------------------------------------------------
// Attention (single pass): grid (32 qtiles x 32 bh), 256 threads (8 warps 4x2).
// 32-key double-buffered KV tiles; total smem 115.2KB => 2 CTAs/SM.
// ---------------------------------------------------------------------------
#define AAS 136
#define APS 40
#define AT_Q   0
#define AT_KV  (2 * 64 * AAS)
#define AT_KVS (4 * 32 * AAS)
#define AT_P   (AT_KV + 2 * AT_KVS)
#define AT_LP  (AT_P + 2 * 64 * APS)
#define ATTN_SMEM_BYTES (AT_LP * 2 + 512)

__global__ __launch_bounds__(256, 2) void attn_kernel(
    const __nv_bfloat16* __restrict__ Qhg, const __nv_bfloat16* __restrict__ Qlg,
    const __nv_bfloat16* __restrict__ Khg, const __nv_bfloat16* __restrict__ Klg,
    const __nv_bfloat16* __restrict__ Vhg, const __nv_bfloat16* __restrict__ Vlg,
    float* __restrict__ AW, float* __restrict__ invLg,
    __nv_bfloat16* __restrict__ Ohg, __nv_bfloat16* __restrict__ Olg)
{
    extern __shared__ __nv_bfloat16 sm[];
    __nv_bfloat16* Qh = sm + AT_Q;
    __nv_bfloat16* Ql = Qh + 64 * AAS;
    __nv_bfloat16* Ph = sm + AT_P;
    __nv_bfloat16* Pl = Ph + 64 * APS;
    float* lp = (float*)(sm + AT_LP);

    const int tid = threadIdx.x;
    const int lane = tid & 31;
    const int wid = tid >> 5;
    const int wr = wid & 3;
    const int wc = wid >> 2;
    const int qt = blockIdx.x;
    const int bh = blockIdx.y;
    const int b = bh >> 4, h = bh & 15, kv = h >> 2;

    const size_t qrow0 = (size_t)b * T + qt * 64;
    const size_t krow0 = (size_t)b * T;
    const int kcol = kv * 128;

    auto load_kv = [&](int s, size_t row0) {
        __nv_bfloat16* base = sm + AT_KV + s * AT_KVS;
        #pragma unroll
        for (int i = 0; i < 2; i++) {
            int idx = i * 256 + tid;
            int r = idx >> 4, cg = (idx & 15) * 8;
            cp16(smem_u32(&base[r * AAS + cg]),            &Khg[(row0 + r) * KVDIM + kcol + cg]);
            cp16(smem_u32(&base[32*AAS + r * AAS + cg]),   &Klg[(row0 + r) * KVDIM + kcol + cg]);
            cp16(smem_u32(&base[2*32*AAS + r * AAS + cg]), &Vhg[(row0 + r) * KVDIM + kcol + cg]);
            cp16(smem_u32(&base[3*32*AAS + r * AAS + cg]), &Vlg[(row0 + r) * KVDIM + kcol + cg]);
        }
    };

    load_kv(0, krow0);
    CP_COMMIT();
    #pragma unroll
    for (int i = 0; i < 4; i++) {
        int idx = i * 256 + tid;
        int r = idx >> 4, cg = (idx & 15) * 8;
        *reinterpret_cast<uint4*>(&Qh[r * AAS + cg]) =
            *reinterpret_cast<const uint4*>(&Qhg[(qrow0 + r) * DIM + h * 128 + cg]);
        *reinterpret_cast<uint4*>(&Ql[r * AAS + cg]) =
            *reinterpret_cast<const uint4*>(&Qlg[(qrow0 + r) * DIM + h * 128 + cg]);
    }

    float l0 = 0.f, l1 = 0.f;
    float o[8][4] = {};

    const int r0 = wr * 16 + (lane >> 2);
    const int c0 = (lane & 3) * 2;
    const size_t gb = ((size_t)bh * T + (size_t)qt * 64) * T;

    #pragma unroll 1
    for (int kt = 0; kt < 64; kt++) {
        CP_WAIT0();
        __syncthreads();
        if (kt < 63) {
            load_kv((kt + 1) & 1, krow0 + (kt + 1) * 32);
            CP_COMMIT();
        }

        const __nv_bfloat16* Kbh = sm + AT_KV + (kt & 1) * AT_KVS;
        const __nv_bfloat16* Kbl = Kbh + 32 * AAS;
        const __nv_bfloat16* Vbh = Kbh + 2 * 32 * AAS;
        const __nv_bfloat16* Vbl = Kbh + 3 * 32 * AAS;

        float s[2][4];
        #pragma unroll
        for (int nt = 0; nt < 2; nt++)
            #pragma unroll
            for (int j = 0; j < 4; j++) s[nt][j] = 0.f;

        #pragma unroll
        for (int kk = 0; kk < 8; kk++) {
            uint32_t ah[4], al[4];
            int ar = wr * 16 + (lane & 15), ac = kk * 16 + (lane >> 4) * 8;
            ldsm_x4(ah, smem_u32(&Qh[ar * AAS + ac]));
            ldsm_x4(al, smem_u32(&Ql[ar * AAS + ac]));
            int br = wc * 16 + (lane & 15), bc = kk * 16 + (lane >> 4) * 8;
            uint32_t b4h[4], b4l[4];
            ldsm_x4(b4h, smem_u32(&Kbh[br * AAS + bc]));
            ldsm_x4(b4l, smem_u32(&Kbl[br * AAS + bc]));
            uint32_t be_h[2] = {b4h[0], b4h[2]}, bo_h[2] = {b4h[1], b4h[3]};
            uint32_t be_l[2] = {b4l[0], b4l[2]}, bo_l[2] = {b4l[1], b4l[3]};
            mma16816(s[0], ah, be_h); mma16816(s[0], ah, be_l); mma16816(s[0], al, be_h);
            mma16816(s[1], ah, bo_h); mma16816(s[1], ah, bo_l); mma16816(s[1], al, bo_h);
        }

        #pragma unroll
        for (int nt = 0; nt < 2; nt++) {
            s[nt][0] = __expf(s[nt][0]); s[nt][1] = __expf(s[nt][1]);
            s[nt][2] = __expf(s[nt][2]); s[nt][3] = __expf(s[nt][3]);
            l0 += s[nt][0] + s[nt][1];
            l1 += s[nt][2] + s[nt][3];
            int colL = wc * 16 + nt * 8 + c0;
            __nv_bfloat162 h0 = pack_hi(s[nt][0], s[nt][1]), lo0 = pack_lo(s[nt][0], s[nt][1], h0);
            __nv_bfloat162 h1 = pack_hi(s[nt][2], s[nt][3]), lo1 = pack_lo(s[nt][2], s[nt][3], h1);
            *reinterpret_cast<__nv_bfloat162*>(&Ph[r0 * APS + colL]) = h0;
            *reinterpret_cast<__nv_bfloat162*>(&Pl[r0 * APS + colL]) = lo0;
            *reinterpret_cast<__nv_bfloat162*>(&Ph[(r0 + 8) * APS + colL]) = h1;
            *reinterpret_cast<__nv_bfloat162*>(&Pl[(r0 + 8) * APS + colL]) = lo1;
        }
        __syncthreads();

        #pragma unroll
        for (int kc = 0; kc < 2; kc++) {
            uint32_t ph4[4], pl4[4];
            int pr = wr * 16 + (lane & 15), pc = kc * 16 + (lane >> 4) * 8;
            ldsm_x4(ph4, smem_u32(&Ph[pr * APS + pc]));
            ldsm_x4(pl4, smem_u32(&Pl[pr * APS + pc]));
            #pragma unroll
            for (int p = 0; p < 4; p++) {
                int vr = kc * 16 + (lane & 15);
                int vc = wc * 64 + p * 16 + (lane >> 4) * 8;
                uint32_t v4h[4], v4l[4];
                ldsm_x4t(v4h, smem_u32(&Vbh[vr * AAS + vc]));
                ldsm_x4t(v4l, smem_u32(&Vbl[vr * AAS + vc]));
                uint32_t be_h[2] = {v4h[0], v4h[1]}, bo_h[2] = {v4h[2], v4h[3]};
                uint32_t be_l[2] = {v4l[0], v4l[1]}, bo_l[2] = {v4l[2], v4l[3]};
                mma16816(o[2*p],   ph4, be_h); mma16816(o[2*p],   ph4, be_l); mma16816(o[2*p],   pl4, be_h);
                mma16816(o[2*p+1], ph4, bo_h); mma16816(o[2*p+1], ph4, bo_l); mma16816(o[2*p+1], pl4, bo_h);
            }
        }

        #pragma unroll
        for (int nt = 0; nt < 2; nt++) {
            int col = kt * 32 + wc * 16 + nt * 8 + c0;
            *reinterpret_cast<float2*>(&AW[gb + (size_t)r0 * T + col]) =
                make_float2(s[nt][0], s[nt][1]);
            *reinterpret_cast<float2*>(&AW[gb + (size_t)(r0 + 8) * T + col]) =
                make_float2(s[nt][2], s[nt][3]);
        }
    }

    l0 += __shfl_xor_sync(0xffffffffu, l0, 1);
    l0 += __shfl_xor_sync(0xffffffffu, l0, 2);
    l1 += __shfl_xor_sync(0xffffffffu, l1, 1);
    l1 += __shfl_xor_sync(0xffffffffu, l1, 2);
    __syncthreads();
    if ((lane & 3) == 0) {
        lp[wc * 64 + r0] = l0;
        lp[wc * 64 + r0 + 8] = l1;
    }
    __syncthreads();

    if (tid < 64) {
        float il = 1.f / (lp[tid] + lp[64 + tid]);
        invLg[(size_t)bh * T + qt * 64 + tid] = il;
    }

    const float ilA = 1.f / (lp[r0] + lp[64 + r0]);
    const float ilB = 1.f / (lp[r0 + 8] + lp[64 + r0 + 8]);

    #pragma unroll
    for (int nt = 0; nt < 8; nt++) {
        int c = h * 128 + wc * 64 + nt * 8 + c0;
        float v00 = o[nt][0] * ilA, v01 = o[nt][1] * ilA;
        float v10 = o[nt][2] * ilB, v11 = o[nt][3] * ilB;
        __nv_bfloat162 h0 = pack_hi(v00, v01), l0v = pack_lo(v00, v01, h0);
        __nv_bfloat162 h1 = pack_hi(v10, v11), l1v = pack_lo(v10, v11, h1);
        *reinterpret_cast<__nv_bfloat162*>(&Ohg[(qrow0 + r0) * DIM + c]) = h0;
        *reinterpret_cast<__nv_bfloat162*>(&Olg[(qrow0 + r0) * DIM + c]) = l0v;
        *reinterpret_cast<__nv_bfloat162*>(&Ohg[(qrow0 + r0 + 8) * DIM + c]) = h1;
        *reinterpret_cast<__nv_bfloat162*>(&Olg[(qrow0 + r0 + 8) * DIM + c]) = l1v;
    }
}

// ---------------------------------------------------------------------------
// launch
// ---------------------------------------------------------------------------
extern "C" void kernel_launch(void* const* d_in, const int* in_sizes, int n_in,
                              void* d_out, int out_size)
{
    const float* q  = (const float*)d_in[0];
    const float* k  = (const float*)d_in[1];
    const float* v  = (const float*)d_in[2];
    const float* Wq = (const float*)d_in[3];
    const float* bq = (const float*)d_in[4];
    const float* Wk = (const float*)d_in[5];
    const float* bk = (const float*)d_in[6];
    const float* Wv = (const float*)d_in[7];
    const float* bv = (const float*)d_in[8];
    const float* Wo = (const float*)d_in[9];
    const float* bo = (const float*)d_in[10];

    float* out   = (float*)d_out;
    float* attnW = out + (size_t)BT * DIM;

    __nv_bfloat16 *qh, *ql, *kh, *kl, *vh, *vl;
    __nv_bfloat16 *Wqh, *Wql, *Wkh, *Wkl, *Wvh, *Wvl, *Woh, *Wol;
    __nv_bfloat16 *Qh, *Ql, *Kh, *Kl, *Vh, *Vl, *Oh, *Ol;
    float* invL;
    cudaGetSymbolAddress((void**)&qh, g_qh);   cudaGetSymbolAddress((void**)&ql, g_ql);
    cudaGetSymbolAddress((void**)&kh, g_kh);   cudaGetSymbolAddress((void**)&kl, g_kl);
    cudaGetSymbolAddress((void**)&vh, g_vh);   cudaGetSymbolAddress((void**)&vl, g_vl);
    cudaGetSymbolAddress((void**)&Wqh, g_Wqh); cudaGetSymbolAddress((void**)&Wql, g_Wql);
    cudaGetSymbolAddress((void**)&Wkh, g_Wkh); cudaGetSymbolAddress((void**)&Wkl, g_Wkl);
    cudaGetSymbolAddress((void**)&Wvh, g_Wvh); cudaGetSymbolAddress((void**)&Wvl, g_Wvl);
    cudaGetSymbolAddress((void**)&Woh, g_Woh); cudaGetSymbolAddress((void**)&Wol, g_Wol);
    cudaGetSymbolAddress((void**)&Qh, g_Qh);   cudaGetSymbolAddress((void**)&Ql, g_Ql);
    cudaGetSymbolAddress((void**)&Kh, g_Kh);   cudaGetSymbolAddress((void**)&Kl, g_Kl);
    cudaGetSymbolAddress((void**)&Vh, g_Vh);   cudaGetSymbolAddress((void**)&Vl, g_Vl);
    cudaGetSymbolAddress((void**)&Oh, g_Oh);   cudaGetSymbolAddress((void**)&Ol, g_Ol);
    cudaGetSymbolAddress((void**)&invL, g_invL);

    cudaFuncSetAttribute(gemm_qkv_kernel, cudaFuncAttributeMaxDynamicSharedMemorySize,
                         G_SMEM_BYTES);
    cudaFuncSetAttribute(gemm_wo_norm_kernel, cudaFuncAttributeMaxDynamicSharedMemorySize,
                         G_SMEM_BYTES);
    cudaFuncSetAttribute(attn_kernel, cudaFuncAttributeMaxDynamicSharedMemorySize,
                         ATTN_SMEM_BYTES);

    const float scale = 0.08838834764831845f;  // 1/sqrt(128)

    // splits (fp32 -> bf16 hi/lo): 3 fused launches
    const int nBD = BT * DIM / 4, nDD = DIM * DIM / 4, nDK = DIM * KVDIM / 4;
    split3_kernel<<<dim3((nBD + 255) / 256, 3), 256>>>(
        q, qh, ql, k, kh, kl, v, vh, vl, nBD);
    split3_kernel<<<dim3((nDD + 255) / 256, 2), 256>>>(
        Wq, Wqh, Wql, Wo, Woh, Wol, nullptr, nullptr, nullptr, nDD);
    split3_kernel<<<dim3((nDK + 255) / 256, 2), 256>>>(
        Wk, Wkh, Wkl, Wv, Wvh, Wvl, nullptr, nullptr, nullptr, nDK);

    // fused Q/K/V projections (one launch, one wave tail)
    gemm_qkv_kernel<<<768, 256, G_SMEM_BYTES>>>(
        qh, ql, Wqh, Wql, bq, Qh, Ql,
        kh, kl, Wkh, Wkl, bk, Kh, Kl,
        vh, vl, Wvh, Wvl, bv, Vh, Vl,
        scale);

    // attention (raw exp -> AW, O pre-split & scaled)
    attn_kernel<<<dim3(T / 64, 32), 256, ATTN_SMEM_BYTES>>>(
        Qh, Ql, Kh, Kl, Vh, Vl, attnW, invL, Oh, Ol);

    // fused Wo projection + AW normalize (memory-bound CTAs soak idle HBM)
    gemm_wo_norm_kernel<<<512 + NORM_CTAS, 256, G_SMEM_BYTES>>>(
        Oh, Ol, Woh, Wol, bo, out, attnW, invL);
}